// round 13
// baseline (speedup 1.0000x reference)
#include <cuda_runtime.h>
#include <math.h>

#define H 1024
#define W 1024
#define NB 4
#define NPIX (H*W)          /* 1048576 = 2^20 */
#define TOT  (NB*NPIX)      /* 4194304 */

// ---------------- scratch (static device globals; no runtime allocation) -----
__device__ float    g_blur[TOT];      // 16 MB
__device__ int      g_state[TOT];     // 16 MB   0=none 1=weak 2=strong
__device__ unsigned g_queue[TOT];     // 16 MB   BFS queue slots
__device__ unsigned g_qhead, g_qtail, g_qproc, g_bar1, g_bar2;

// neighbor offsets for direction k = round(angle/45) mod 8
// k: 0:(0,1) 1:(-1,1) 2:(-1,0) 3:(-1,-1) 4:(0,-1) 5:(1,-1) 6:(1,0) 7:(1,1)
__constant__ int c_dr[8] = {0,-1,-1,-1, 0, 1, 1, 1};
__constant__ int c_dc[8] = {1, 1, 0,-1,-1,-1, 0, 1};

struct GaussW { float w[25]; };

// ---------------- stage 1: grayscale + 5x5 gaussian, reflect padding --------
__global__ void k_gray_blur(const float* __restrict__ x, GaussW gw) {
    __shared__ float s[36][37];
    const int bx = blockIdx.x * 32, by = blockIdx.y * 32, b = blockIdx.z;
    const float* xr = x + (size_t)b * 3 * NPIX;
    const int tid = threadIdx.y * 32 + threadIdx.x;

    for (int i = tid; i < 36 * 36; i += 256) {
        int r = i / 36, c = i - r * 36;
        int gy = by - 2 + r, gx = bx - 2 + c;
        gy = gy < 0 ? -gy : (gy > H - 1 ? 2 * (H - 1) - gy : gy);   // numpy 'reflect'
        gx = gx < 0 ? -gx : (gx > W - 1 ? 2 * (W - 1) - gx : gx);
        int idx = gy * W + gx;
        s[r][c] = 0.299f * xr[idx] + 0.587f * xr[NPIX + idx] + 0.114f * xr[2 * NPIX + idx];
    }
    __syncthreads();

    const int tx = threadIdx.x;
    for (int k = 0; k < 4; k++) {
        int oy = threadIdx.y + 8 * k;
        float acc = 0.f;
        #pragma unroll
        for (int r = 0; r < 5; r++)
            #pragma unroll
            for (int c = 0; c < 5; c++)
                acc += gw.w[r * 5 + c] * s[oy + r][tx + c];
        g_blur[(size_t)b * NPIX + (size_t)(by + oy) * W + bx + tx] = acc;
    }
}

// ------- stage 2: sobel (edge pad) + magnitude + NMS + thresholds -----------
__global__ void k_sobel_nms(float* __restrict__ outMag) {
    __shared__ float bs[36][37];   // blurred, edge-clamped, halo 2
    __shared__ float ms[34][35];   // magnitude (0 outside image), halo 1
    __shared__ float gxs[34][35];
    __shared__ float gys[34][35];
    const int bx = blockIdx.x * 32, by = blockIdx.y * 32, b = blockIdx.z;
    const float* bl = g_blur + (size_t)b * NPIX;
    const int tid = threadIdx.y * 32 + threadIdx.x;

    for (int i = tid; i < 36 * 36; i += 256) {
        int r = i / 36, c = i - r * 36;
        int gy = min(max(by - 2 + r, 0), H - 1);   // 'edge' padding
        int gx = min(max(bx - 2 + c, 0), W - 1);
        bs[r][c] = bl[gy * W + gx];
    }
    __syncthreads();

    for (int i = tid; i < 34 * 34; i += 256) {
        int r = i / 34, c = i - r * 34;
        int iy = by - 1 + r, ix = bx - 1 + c;
        float m = 0.f, gxv = 0.f, gyv = 0.f;
        if ((unsigned)iy < (unsigned)H && (unsigned)ix < (unsigned)W) {
            float a00 = bs[r][c],     a01 = bs[r][c + 1],     a02 = bs[r][c + 2];
            float a10 = bs[r + 1][c],                         a12 = bs[r + 1][c + 2];
            float a20 = bs[r + 2][c], a21 = bs[r + 2][c + 1], a22 = bs[r + 2][c + 2];
            gxv = (a02 - a00) + 2.f * (a12 - a10) + (a22 - a20);
            gyv = (a20 - a00) + 2.f * (a21 - a01) + (a22 - a02);
            m = sqrtf(gxv * gxv + gyv * gyv + 1e-6f);
        }
        ms[r][c] = m; gxs[r][c] = gxv; gys[r][c] = gyv;
    }
    __syncthreads();

    const int tx = threadIdx.x;
    for (int k = 0; k < 4; k++) {
        int oy = threadIdx.y + 8 * k;
        int r = oy + 1, c = tx + 1;
        float gxv = gxs[r][c], gyv = gys[r][c];
        float deg = atan2f(gyv, gxv) * 57.29577951308232f;   // jnp.degrees
        int kk = (int)rintf(deg / 45.0f);                    // jnp.round (half-even)
        int pos = kk & 7, neg = (kk + 4) & 7;
        float mc = ms[r][c];
        float csp = mc - ms[r + c_dr[pos]][c + c_dc[pos]];
        float csn = mc - ms[r + c_dr[neg]][c + c_dc[neg]];
        float mo = (fminf(csp, csn) > 0.0f) ? mc : 0.0f;
        int oidx = b * NPIX + (by + oy) * W + bx + tx;
        outMag[oidx] = mo;
        g_state[oidx] = (mo > 0.2f) ? 2 : ((mo > 0.1f) ? 1 : 0);
    }
}

// ---------------- stage 3: hysteresis = closure of strong through weak ------
__global__ void k_reset() {
    if (threadIdx.x == 0) { g_qhead = 0; g_qtail = 0; g_qproc = 0; g_bar1 = 0; g_bar2 = 0; }
}

// 128 blocks x 256 threads: <= SM count, all co-resident -> software barrier ok
__global__ void __launch_bounds__(256, 1) k_hyst(float* __restrict__ edges) {
    const int gtid = blockIdx.x * blockDim.x + threadIdx.x;
    const int nthr = gridDim.x * blockDim.x;

    // phase 0: clear queue sentinels
    for (int i = gtid; i < TOT; i += nthr) g_queue[i] = 0xFFFFFFFFu;

    __syncthreads();
    if (threadIdx.x == 0) {
        __threadfence();
        atomicAdd(&g_bar1, 1u);
        while (atomicAdd(&g_bar1, 0u) < gridDim.x) { }
    }
    __syncthreads();

    // phase 1: seed sweep — promote weak pixels touching strong, enqueue them
    for (int i = gtid; i < TOT; i += nthr) {
        if (__ldcg(&g_state[i]) == 1) {
            int y = (i >> 10) & 1023, xx = i & 1023;
            int base = i & ~(NPIX - 1);
            bool near_strong = false;
            #pragma unroll
            for (int d = 0; d < 8; d++) {
                int ny = y + c_dr[d], nx = xx + c_dc[d];
                if ((unsigned)ny < 1024u && (unsigned)nx < 1024u &&
                    __ldcg(&g_state[base + (ny << 10) + nx]) == 2)
                    near_strong = true;
            }
            if (near_strong && atomicCAS(&g_state[i], 1, 2) == 1) {
                unsigned pos = atomicAdd(&g_qtail, 1u);
                ((volatile unsigned*)g_queue)[pos] = (unsigned)i;
            }
        }
    }

    __syncthreads();
    if (threadIdx.x == 0) {
        __threadfence();
        atomicAdd(&g_bar2, 1u);
        while (atomicAdd(&g_bar2, 0u) < gridDim.x) { }
    }
    __syncthreads();

    // phase 2: async BFS over the work queue
    bool done = false;
    while (!done) {
        unsigned t = atomicAdd(&g_qhead, 1u);
        for (;;) {
            unsigned tail = *(volatile unsigned*)&g_qtail;
            if (t < tail) break;
            unsigned p = *(volatile unsigned*)&g_qproc;      // read proc BEFORE tail
            unsigned tail2 = *(volatile unsigned*)&g_qtail;
            if (p == tail2 && t >= tail2) { done = true; break; }  // fully drained
            __nanosleep(64);
        }
        if (done) break;
        unsigned v;
        while ((v = ((volatile unsigned*)g_queue)[t]) == 0xFFFFFFFFu) { }
        int y = (v >> 10) & 1023, xx = v & 1023;
        int base = (int)(v & ~(unsigned)(NPIX - 1));
        #pragma unroll
        for (int d = 0; d < 8; d++) {
            int ny = y + c_dr[d], nx = xx + c_dc[d];
            if ((unsigned)ny < 1024u && (unsigned)nx < 1024u) {
                int ni = base + (ny << 10) + nx;
                if (__ldcg(&g_state[ni]) == 1 && atomicCAS(&g_state[ni], 1, 2) == 1) {
                    unsigned pos = atomicAdd(&g_qtail, 1u);
                    ((volatile unsigned*)g_queue)[pos] = (unsigned)ni;
                }
            }
        }
        __threadfence();               // CAS + slot writes visible before proc count
        atomicAdd(&g_qproc, 1u);
    }

    // phase 3: state is final once drained — write edges
    __threadfence();
    for (int i = gtid; i < TOT; i += nthr)
        edges[i] = (__ldcg(&g_state[i]) == 2) ? 1.0f : 0.0f;
}

// ---------------------------------------------------------------------------
extern "C" void kernel_launch(void* const* d_in, const int* in_sizes, int n_in,
                              void* d_out, int out_size) {
    const float* x = (const float*)d_in[0];
    float* out = (float*)d_out;

    // Gaussian weights, replicating numpy float32 construction
    GaussW gw;
    float g1[5];
    for (int i = 0; i < 5; i++) {
        double d = (double)i - 2.0;
        g1[i] = (float)exp(-d * d / 2.0);
    }
    float s = 0.f;
    for (int i = 0; i < 5; i++) s += g1[i];
    for (int i = 0; i < 5; i++) g1[i] = g1[i] / s;
    for (int i = 0; i < 5; i++)
        for (int j = 0; j < 5; j++)
            gw.w[i * 5 + j] = g1[i] * g1[j];

    dim3 blk(32, 8), grd(32, 32, NB);
    k_gray_blur<<<grd, blk>>>(x, gw);
    k_sobel_nms<<<grd, blk>>>(out);            // magnitude -> out[0 .. TOT)
    k_reset<<<1, 32>>>();
    k_hyst<<<128, 256>>>(out + TOT);           // edges -> out[TOT .. 2*TOT)
    (void)in_sizes; (void)n_in; (void)out_size;
}